// round 14
// baseline (speedup 1.0000x reference)
#include <cuda_runtime.h>
#include <cuda_bf16.h>

// CBOW negative-sampling loss, round 14: bf16 tables + reg-diet main (occ 100%)
// + MLP-8 convert. Two-launch reduce (frozen).
#define VOCAB 50000
#define DIM   50
#define BATCH 131072
#define CTX   10
#define NEG   10

#define THREADS  128
#define WPB      (THREADS / 32)          // 4 samples per block
#define NBLOCKS  (BATCH / WPB)           // 32768
#define RED_B    256
#define RED_T    512                     // 256*512 = 131072 exact

#define RSTRIDE  28                      // 28 floats = 112B rows (16B aligned)

#define N4TAB    (VOCAB * DIM / 4)       // 625000 float4 per table
#define CVT_TOT  (2 * N4TAB)             // 1.25M float4
#define CVT_T    256
#define CVT_V    8                       // float4 per thread (MLP=8)
#define CVT_B    ((CVT_TOT + CVT_T * CVT_V - 1) / (CVT_T * CVT_V))  // 611

__device__ __align__(16) __nv_bfloat162 g_inB[VOCAB * 25];   // 5 MB bf16 in_embed
__device__ __align__(16) __nv_bfloat162 g_outB[VOCAB * 25];  // 5 MB bf16 out_embed
__device__ __align__(16) float g_wl[BATCH];   // per-sample loss
__device__ __align__(16) float g_red[RED_B];  // reduce partials
__device__ unsigned            g_cnt = 0;     // last-block counter (self-resetting)

// ---- table repack fp32 -> bf16, 8 front-batched loads per thread ----
__global__ __launch_bounds__(CVT_T)
void cbow_convert(const float4* __restrict__ inW4, const float4* __restrict__ outW4)
{
    const int base = blockIdx.x * CVT_T * CVT_V + threadIdx.x;
    float4 v[CVT_V];
    int    idx[CVT_V];
    #pragma unroll
    for (int k = 0; k < CVT_V; k++) {
        int i = base + k * CVT_T;
        idx[k] = i;
        if (i < N4TAB)            v[k] = __ldg(&inW4[i]);
        else if (i < CVT_TOT)     v[k] = __ldg(&outW4[i - N4TAB]);
        else                      v[k] = make_float4(0.f, 0.f, 0.f, 0.f);
    }
    #pragma unroll
    for (int k = 0; k < CVT_V; k++) {
        int i = idx[k];
        if (i >= CVT_TOT) continue;
        __nv_bfloat162 lo = __floats2bfloat162_rn(v[k].x, v[k].y);
        __nv_bfloat162 hi = __floats2bfloat162_rn(v[k].z, v[k].w);
        uint2 packed = make_uint2(*reinterpret_cast<unsigned*>(&lo),
                                  *reinterpret_cast<unsigned*>(&hi));
        if (i < N4TAB) reinterpret_cast<uint2*>(g_inB)[i] = packed;
        else           reinterpret_cast<uint2*>(g_outB)[i - N4TAB] = packed;
    }
}

__device__ __forceinline__ float2 bf2f(__nv_bfloat162 v) {
    return __bfloat1622float2(v);
}

__global__ __launch_bounds__(THREADS, 16)    // cap 32 regs -> 2048 thr/SM (100% occ)
void cbow_main(const int* __restrict__ ctx,
               const int* __restrict__ pos,
               const int* __restrict__ neg)
{
    __shared__ int s_ctx[WPB * CTX];
    __shared__ int s_neg[WPB * NEG];
    __shared__ int s_pos[WPB];
    __shared__ __align__(16) float s_red[WPB][11 * RSTRIDE];

    const int tid  = threadIdx.x;
    const int lane = tid & 31;
    const int warp = tid >> 5;
    const int B0   = blockIdx.x * WPB;
    const unsigned FULL = 0xffffffffu;

    // ---- stage this block's indices, coalesced ----
    if (tid < WPB * CTX) s_ctx[tid] = __ldg(&ctx[B0 * CTX + tid]);
    if (tid < WPB * NEG) s_neg[tid] = __ldg(&neg[B0 * NEG + tid]);
    if (tid < WPB)       s_pos[tid] = __ldg(&pos[B0 + tid]);
    __syncthreads();

    const bool act = (lane < 25);            // 25 lanes x bf16x2 = 50 dims
    const __nv_bfloat162 Z2 = __floats2bfloat162_rn(0.f, 0.f);
    float* const red = &s_red[warp][lane];   // transpose column base for this lane

    // ---- context mean: 2 groups of 5 gathers, fold immediately ----
    float2 cv = make_float2(0.f, 0.f);
    #pragma unroll
    for (int g = 0; g < 2; g++) {
        __nv_bfloat162 t[5];
        #pragma unroll
        for (int c = 0; c < 5; c++) {
            int r = s_ctx[warp * CTX + g * 5 + c];
            t[c] = act ? __ldg(&g_inB[r * 25 + lane]) : Z2;
        }
        #pragma unroll
        for (int c = 0; c < 5; c++) {
            float2 f = bf2f(t[c]);
            cv.x += f.x; cv.y += f.y;
        }
    }
    cv.x *= (1.0f / CTX);
    cv.y *= (1.0f / CTX);

    // ---- 11 out_embed dots in groups of 4/4/3; partials go STRAIGHT to smem
    //      (no live p[] registers -> fits the 32-reg cap) ----
    {
        __nv_bfloat162 t[4];
        {
            int r = s_pos[warp];
            t[0] = act ? __ldg(&g_outB[r * 25 + lane]) : Z2;
        }
        #pragma unroll
        for (int k = 0; k < 3; k++) {
            int r = s_neg[warp * NEG + k];
            t[k + 1] = act ? __ldg(&g_outB[r * 25 + lane]) : Z2;
        }
        #pragma unroll
        for (int j = 0; j < 4; j++) {
            float2 f = bf2f(t[j]);
            if (act) red[j * RSTRIDE] = cv.x * f.x + cv.y * f.y;
        }
    }
    {
        __nv_bfloat162 t[4];
        #pragma unroll
        for (int k = 0; k < 4; k++) {
            int r = s_neg[warp * NEG + 3 + k];
            t[k] = act ? __ldg(&g_outB[r * 25 + lane]) : Z2;
        }
        #pragma unroll
        for (int j = 0; j < 4; j++) {
            float2 f = bf2f(t[j]);
            if (act) red[(4 + j) * RSTRIDE] = cv.x * f.x + cv.y * f.y;
        }
    }
    {
        __nv_bfloat162 t[3];
        #pragma unroll
        for (int k = 0; k < 3; k++) {
            int r = s_neg[warp * NEG + 7 + k];
            t[k] = act ? __ldg(&g_outB[r * 25 + lane]) : Z2;
        }
        #pragma unroll
        for (int j = 0; j < 3; j++) {
            float2 f = bf2f(t[j]);
            if (act) red[(8 + j) * RSTRIDE] = cv.x * f.x + cv.y * f.y;
        }
    }
    __syncwarp();

    // ---- lane j owns dot j: horizontal sum + log-sigmoid ----
    float term = 0.f;
    if (lane <= NEG) {
        const float* row = &s_red[warp][lane * RSTRIDE];
        float4 a = *(const float4*)(row);
        float4 b = *(const float4*)(row + 4);
        float4 c = *(const float4*)(row + 8);
        float4 d = *(const float4*)(row + 12);
        float4 e = *(const float4*)(row + 16);
        float4 f = *(const float4*)(row + 20);
        float s = ((a.x + a.y) + (a.z + a.w)) + ((b.x + b.y) + (b.z + b.w))
                + ((c.x + c.y) + (c.z + c.w)) + ((d.x + d.y) + (d.z + d.w))
                + ((e.x + e.y) + (e.z + e.w)) + ((f.x + f.y) + (f.z + f.w))
                + row[24];
        float arg = (lane == 0) ? s : -s;    // pos: +score, negs: -score
        float sg  = 1.0f / (1.0f + __expf(-arg));
        term = __logf(sg + 1e-10f);
    }
    #pragma unroll
    for (int o = 8; o > 0; o >>= 1)          // sum lanes 0..15 (11..15 zero)
        term += __shfl_xor_sync(FULL, term, o);

    if (lane == 0) g_wl[B0 + warp] = term;   // warp-granular retirement
}

__global__ __launch_bounds__(RED_T)
void cbow_reduce(float* __restrict__ out)
{
    __shared__ float s[RED_T / 32];
    __shared__ bool  isLast;
    const int tid  = threadIdx.x;
    const int lane = tid & 31;
    const int warp = tid >> 5;
    const unsigned FULL = 0xffffffffu;

    float t = g_wl[blockIdx.x * RED_T + tid];
    #pragma unroll
    for (int o = 16; o > 0; o >>= 1)
        t += __shfl_xor_sync(FULL, t, o);
    if (lane == 0) s[warp] = t;
    __syncthreads();
    if (tid < 32) {
        float v = (tid < RED_T / 32) ? s[tid] : 0.f;
        #pragma unroll
        for (int o = 16; o > 0; o >>= 1)
            v += __shfl_xor_sync(FULL, v, o);
        if (tid == 0) {
            g_red[blockIdx.x] = v;
            __threadfence();
            unsigned old = atomicAdd(&g_cnt, 1u);
            isLast = (old == RED_B - 1);
        }
    }
    __syncthreads();

    if (isLast && tid < 32) {                 // deterministic fixed-order final sum
        float v = 0.f;
        #pragma unroll
        for (int i = 0; i < RED_B / 32; i++)
            v += __ldcg(&g_red[tid + i * 32]);
        #pragma unroll
        for (int o = 16; o > 0; o >>= 1)
            v += __shfl_xor_sync(FULL, v, o);
        if (tid == 0) {
            out[0] = -v / (float)BATCH;
            g_cnt = 0;                        // reset for next graph replay
        }
    }
}

extern "C" void kernel_launch(void* const* d_in, const int* in_sizes, int n_in,
                              void* d_out, int out_size)
{
    const int*   ctx  = (const int*)d_in[0];   // [B, CTX]
    const int*   pos  = (const int*)d_in[1];   // [B]
    const int*   neg  = (const int*)d_in[2];   // [B, NEG]
    const float* inW  = (const float*)d_in[3]; // [VOCAB, DIM]
    const float* outW = (const float*)d_in[4]; // [VOCAB, DIM]
    float* out = (float*)d_out;

    cbow_convert<<<CVT_B, CVT_T>>>((const float4*)inW, (const float4*)outW);
    cbow_main<<<NBLOCKS, THREADS>>>(ctx, pos, neg);
    cbow_reduce<<<RED_B, RED_T>>>(out);
}

// round 16
// speedup vs baseline: 1.6919x; 1.6919x over previous
#include <cuda_runtime.h>
#include <cuda_bf16.h>

// CBOW negative-sampling loss, round 16: R15 (4 samples/warp, padded bf16 128B rows)
// with the staging-guard bug fixed (strided loops; SPB*CTX=160 > 128 threads).
#define VOCAB 50000
#define DIM   50
#define BATCH 131072
#define CTX   10
#define NEG   10

#define THREADS  128
#define SPB      16                      // samples per block: 4 warps x 4 groups
#define NBLOCKS  (BATCH / SPB)           // 8192
#define NWL      (BATCH / 4)             // 32768 per-warp loss sums
#define RED_B    64
#define RED_T    512                     // 64*512 = 32768 exact

// padded row: 64 bf16 = 128B = 8 uint4 ; dims 50..63 are zero
#define ROW_U4   8
#define CV_OUT   (2 * VOCAB * 16)        // total uint2 outputs (16 per row per table)
#define CVT_T    256
#define CVT_V    4
#define CVT_B    ((CV_OUT + CVT_T * CVT_V - 1) / (CVT_T * CVT_V))

__device__ __align__(16) uint4 g_in4[VOCAB * ROW_U4];    // 6.4 MB padded bf16
__device__ __align__(16) uint4 g_out4[VOCAB * ROW_U4];   // 6.4 MB padded bf16
__device__ __align__(16) float g_wl[NWL];                // per-warp loss sums
__device__ __align__(16) float g_red[RED_B];
__device__ unsigned            g_cnt = 0;                // self-resetting counter

// ---- repack fp32 [V,50] -> padded bf16 [V,64], zeros in pad ----
__global__ __launch_bounds__(CVT_T)
void cbow_convert(const float2* __restrict__ in2, const float2* __restrict__ out2)
{
    const int base = blockIdx.x * CVT_T * CVT_V + threadIdx.x;
    float2 a[CVT_V], b[CVT_V];
    #pragma unroll
    for (int k = 0; k < CVT_V; k++) {
        int o = base + k * CVT_T;
        a[k] = make_float2(0.f, 0.f);
        b[k] = make_float2(0.f, 0.f);
        if (o < CV_OUT) {
            int oo = (o < VOCAB * 16) ? o : o - VOCAB * 16;
            const float2* src = (o < VOCAB * 16) ? in2 : out2;
            int row = oo >> 4, seg = oo & 15;          // seg: which 4-float chunk
            if (seg * 2 < 25)     a[k] = __ldg(&src[row * 25 + seg * 2]);
            if (seg * 2 + 1 < 25) b[k] = __ldg(&src[row * 25 + seg * 2 + 1]);
        }
    }
    #pragma unroll
    for (int k = 0; k < CVT_V; k++) {
        int o = base + k * CVT_T;
        if (o >= CV_OUT) continue;
        int oo = (o < VOCAB * 16) ? o : o - VOCAB * 16;
        uint2* dst = (o < VOCAB * 16) ? (uint2*)g_in4 : (uint2*)g_out4;
        __nv_bfloat162 lo = __floats2bfloat162_rn(a[k].x, a[k].y);
        __nv_bfloat162 hi = __floats2bfloat162_rn(b[k].x, b[k].y);
        dst[oo] = make_uint2(*reinterpret_cast<unsigned*>(&lo),
                             *reinterpret_cast<unsigned*>(&hi));
    }
}

__device__ __forceinline__ void acc4(float2& c0, float2& c1, float2& c2, float2& c3,
                                     uint4 v)
{
    float2 f0 = __bfloat1622float2(*reinterpret_cast<__nv_bfloat162*>(&v.x));
    float2 f1 = __bfloat1622float2(*reinterpret_cast<__nv_bfloat162*>(&v.y));
    float2 f2 = __bfloat1622float2(*reinterpret_cast<__nv_bfloat162*>(&v.z));
    float2 f3 = __bfloat1622float2(*reinterpret_cast<__nv_bfloat162*>(&v.w));
    c0.x += f0.x; c0.y += f0.y;  c1.x += f1.x; c1.y += f1.y;
    c2.x += f2.x; c2.y += f2.y;  c3.x += f3.x; c3.y += f3.y;
}

__device__ __forceinline__ float dot4(float2 c0, float2 c1, float2 c2, float2 c3,
                                      uint4 v)
{
    float2 f0 = __bfloat1622float2(*reinterpret_cast<__nv_bfloat162*>(&v.x));
    float2 f1 = __bfloat1622float2(*reinterpret_cast<__nv_bfloat162*>(&v.y));
    float2 f2 = __bfloat1622float2(*reinterpret_cast<__nv_bfloat162*>(&v.z));
    float2 f3 = __bfloat1622float2(*reinterpret_cast<__nv_bfloat162*>(&v.w));
    return (c0.x * f0.x + c0.y * f0.y) + (c1.x * f1.x + c1.y * f1.y)
         + (c2.x * f2.x + c2.y * f2.y) + (c3.x * f3.x + c3.y * f3.y);
}

__global__ __launch_bounds__(THREADS, 12)
void cbow_main(const int* __restrict__ ctx,
               const int* __restrict__ pos,
               const int* __restrict__ neg)
{
    __shared__ int s_ctx[SPB * CTX];
    __shared__ int s_neg[SPB * NEG];
    __shared__ int s_pos[SPB];
    __shared__ __align__(16) float s_red[4][44 * 8];   // [warp][term][8 lanes]

    const int tid  = threadIdx.x;
    const int lane = tid & 31;
    const int warp = tid >> 5;
    const int grp  = lane >> 3;          // 4 samples per warp
    const int li   = lane & 7;           // 8 lanes per sample, uint4 each = 128B row
    const int B0   = blockIdx.x * SPB;
    const unsigned FULL = 0xffffffffu;

    // ---- stage indices: STRIDED loops (SPB*CTX=160 > THREADS=128 -> R15 bug) ----
    for (int i = tid; i < SPB * CTX; i += THREADS) s_ctx[i] = __ldg(&ctx[B0 * CTX + i]);
    for (int i = tid; i < SPB * NEG; i += THREADS) s_neg[i] = __ldg(&neg[B0 * NEG + i]);
    if (tid < SPB) s_pos[tid] = __ldg(&pos[B0 + tid]);
    __syncthreads();

    const int s = warp * 4 + grp;        // sample within block
    float* const red = &s_red[warp][grp * 88 + li];    // term stride 8 floats

    // ---- context mean: 2 groups of 5 LDG.128 (each serves 4 samples) ----
    float2 c0 = {0,0}, c1 = {0,0}, c2 = {0,0}, c3 = {0,0};
    #pragma unroll
    for (int g = 0; g < 2; g++) {
        uint4 t[5];
        #pragma unroll
        for (int c = 0; c < 5; c++) {
            int r = s_ctx[s * CTX + g * 5 + c];
            t[c] = __ldg(&g_in4[r * ROW_U4 + li]);
        }
        #pragma unroll
        for (int c = 0; c < 5; c++) acc4(c0, c1, c2, c3, t[c]);
    }
    c0.x *= 0.1f; c0.y *= 0.1f;  c1.x *= 0.1f; c1.y *= 0.1f;
    c2.x *= 0.1f; c2.y *= 0.1f;  c3.x *= 0.1f; c3.y *= 0.1f;

    // ---- 11 dots in groups of 4/4/3; 8-dim partials straight to transpose smem ----
    {
        uint4 t[4];
        t[0] = __ldg(&g_out4[s_pos[s] * ROW_U4 + li]);
        #pragma unroll
        for (int k = 0; k < 3; k++)
            t[k + 1] = __ldg(&g_out4[s_neg[s * NEG + k] * ROW_U4 + li]);
        #pragma unroll
        for (int j = 0; j < 4; j++) red[j * 8] = dot4(c0, c1, c2, c3, t[j]);
    }
    {
        uint4 t[4];
        #pragma unroll
        for (int k = 0; k < 4; k++)
            t[k] = __ldg(&g_out4[s_neg[s * NEG + 3 + k] * ROW_U4 + li]);
        #pragma unroll
        for (int j = 0; j < 4; j++) red[(4 + j) * 8] = dot4(c0, c1, c2, c3, t[j]);
    }
    {
        uint4 t[3];
        #pragma unroll
        for (int k = 0; k < 3; k++)
            t[k] = __ldg(&g_out4[s_neg[s * NEG + 7 + k] * ROW_U4 + li]);
        #pragma unroll
        for (int j = 0; j < 3; j++) red[(8 + j) * 8] = dot4(c0, c1, c2, c3, t[j]);
    }
    __syncwarp();

    // ---- 44 terms: lane handles term=lane (+ term=lane+32 for lanes 0..11) ----
    float total;
    {
        int t0 = lane;                       // terms 0..31
        int j0 = t0 % 11;                    // j==0 -> positive score
        const float* r0 = &s_red[warp][t0 * 8];
        float4 A  = *(const float4*)(r0);
        float4 Bv = *(const float4*)(r0 + 4);
        float sc = ((A.x + A.y) + (A.z + A.w)) + ((Bv.x + Bv.y) + (Bv.z + Bv.w));
        float arg = (j0 == 0) ? sc : -sc;
        total = __logf(1.0f / (1.0f + __expf(-arg)) + 1e-10f);
    }
    {
        int t1 = lane + 32;                  // terms 32..43 on lanes 0..11
        bool v = (t1 < 44);
        int t1c = v ? t1 : 0;
        int j1 = t1c % 11;
        const float* r1 = &s_red[warp][t1c * 8];
        float4 A  = *(const float4*)(r1);
        float4 Bv = *(const float4*)(r1 + 4);
        float sc = ((A.x + A.y) + (A.z + A.w)) + ((Bv.x + Bv.y) + (Bv.z + Bv.w));
        float arg = (j1 == 0) ? sc : -sc;
        float term = __logf(1.0f / (1.0f + __expf(-arg)) + 1e-10f);
        total += v ? term : 0.f;
    }
    #pragma unroll
    for (int o = 16; o > 0; o >>= 1)
        total += __shfl_xor_sync(FULL, total, o);

    if (lane == 0) g_wl[blockIdx.x * 4 + warp] = total;  // 4-sample warp sum
}

__global__ __launch_bounds__(RED_T)
void cbow_reduce(float* __restrict__ out)
{
    __shared__ float sbuf[RED_T / 32];
    __shared__ bool  isLast;
    const int tid  = threadIdx.x;
    const int lane = tid & 31;
    const int warp = tid >> 5;
    const unsigned FULL = 0xffffffffu;

    float t = g_wl[blockIdx.x * RED_T + tid];
    #pragma unroll
    for (int o = 16; o > 0; o >>= 1)
        t += __shfl_xor_sync(FULL, t, o);
    if (lane == 0) sbuf[warp] = t;
    __syncthreads();
    if (tid < 32) {
        float v = (tid < RED_T / 32) ? sbuf[tid] : 0.f;
        #pragma unroll
        for (int o = 16; o > 0; o >>= 1)
            v += __shfl_xor_sync(FULL, v, o);
        if (tid == 0) {
            g_red[blockIdx.x] = v;
            __threadfence();
            unsigned old = atomicAdd(&g_cnt, 1u);
            isLast = (old == RED_B - 1);
        }
    }
    __syncthreads();

    if (isLast && tid < 32) {                 // deterministic fixed-order final sum
        float v = __ldcg(&g_red[tid]) + __ldcg(&g_red[tid + 32]);
        #pragma unroll
        for (int o = 16; o > 0; o >>= 1)
            v += __shfl_xor_sync(FULL, v, o);
        if (tid == 0) {
            out[0] = -v / (float)BATCH;
            g_cnt = 0;                        // reset for next graph replay
        }
    }
}

extern "C" void kernel_launch(void* const* d_in, const int* in_sizes, int n_in,
                              void* d_out, int out_size)
{
    const int*   ctx  = (const int*)d_in[0];   // [B, CTX]
    const int*   pos  = (const int*)d_in[1];   // [B]
    const int*   neg  = (const int*)d_in[2];   // [B, NEG]
    const float* inW  = (const float*)d_in[3]; // [VOCAB, DIM]
    const float* outW = (const float*)d_in[4]; // [VOCAB, DIM]
    float* out = (float*)d_out;

    cbow_convert<<<CVT_B, CVT_T>>>((const float2*)inW, (const float2*)outW);
    cbow_main<<<NBLOCKS, THREADS>>>(ctx, pos, neg);
    cbow_reduce<<<RED_B, RED_T>>>(out);
}